// round 2
// baseline (speedup 1.0000x reference)
#include <cuda_runtime.h>
#include <cuda_bf16.h>

// Accumulators in device globals (no allocation allowed). Zero-initialized at
// module load; the last block resets them to zero after producing the output,
// so every graph replay sees identical starting state (deterministic).
__device__ double       g_loc_sum = 0.0;
__device__ int          g_npos    = 0;
__device__ unsigned int g_ticket  = 0u;

__device__ __forceinline__ float smooth_l1_f(float d) {
    float ad = fabsf(d);
    return (ad < 1.0f) ? 0.5f * d * d : ad - 0.5f;
}

#define GRID_BLOCKS 2368   // 16 CTAs/SM on 148 SMs

// One anchor = 8 floats = 32 bytes = two float4 loads per array.
// Only positive anchors (cls_target > 0) contribute; negatives skip both
// float4 loads entirely (32B sector granularity => real DRAM savings, ~50%
// of anchors are negative for randint(0,2) targets).
__global__ void __launch_bounds__(256) ohem_reduce_kernel(
    const float4* __restrict__ loc_preds,    // [n_anchors*2] float4
    const float4* __restrict__ loc_targets,  // [n_anchors*2] float4
    const int*    __restrict__ cls_targets,  // [n_anchors]
    int n_anchors,
    float* __restrict__ out)
{
    float lsum = 0.0f;
    int   cnt  = 0;

    const int stride = gridDim.x * blockDim.x;
    for (int a = blockIdx.x * blockDim.x + threadIdx.x; a < n_anchors; a += stride) {
        int t = cls_targets[a];
        if (t > 0) {
            cnt++;
            float4 p0 = loc_preds[2 * a];
            float4 p1 = loc_preds[2 * a + 1];
            float4 q0 = loc_targets[2 * a];
            float4 q1 = loc_targets[2 * a + 1];
            lsum += smooth_l1_f(p0.x - q0.x);
            lsum += smooth_l1_f(p0.y - q0.y);
            lsum += smooth_l1_f(p0.z - q0.z);
            lsum += smooth_l1_f(p0.w - q0.w);
            lsum += smooth_l1_f(p1.x - q1.x);
            lsum += smooth_l1_f(p1.y - q1.y);
            lsum += smooth_l1_f(p1.z - q1.z);
            lsum += smooth_l1_f(p1.w - q1.w);
        }
    }

    // Warp reduce
    #pragma unroll
    for (int off = 16; off > 0; off >>= 1) {
        lsum += __shfl_down_sync(0xFFFFFFFFu, lsum, off);
        cnt  += __shfl_down_sync(0xFFFFFFFFu, cnt,  off);
    }

    __shared__ float s_sum[8];
    __shared__ int   s_cnt[8];
    __shared__ bool  s_is_last;
    int wid = threadIdx.x >> 5;
    int lid = threadIdx.x & 31;
    if (lid == 0) { s_sum[wid] = lsum; s_cnt[wid] = cnt; }
    __syncthreads();

    if (wid == 0) {
        lsum = (lid < (blockDim.x >> 5)) ? s_sum[lid] : 0.0f;
        cnt  = (lid < (blockDim.x >> 5)) ? s_cnt[lid] : 0;
        #pragma unroll
        for (int off = 4; off > 0; off >>= 1) {
            lsum += __shfl_down_sync(0xFFFFFFFFu, lsum, off);
            cnt  += __shfl_down_sync(0xFFFFFFFFu, cnt,  off);
        }
        if (lid == 0) {
            atomicAdd(&g_loc_sum, (double)lsum);
            atomicAdd(&g_npos, cnt);
            __threadfence();
            unsigned int ticket = atomicAdd(&g_ticket, 1u);
            s_is_last = (ticket == gridDim.x - 1u);
        }
    }
    __syncthreads();

    // Last block to finish: finalize + reset globals for the next replay.
    if (s_is_last && threadIdx.x == 0) {
        // cls branch is exactly zero for NUM_CLASSES == 1:
        //   ce = logsumexp(single elem) - that elem == 0 exactly in IEEE fp,
        //   so cls_loss == 0 and the hard-negative mining is dead code.
        double n = (double)g_npos;
        out[0] = (n > 0.0) ? (float)(0.2 * g_loc_sum / n) : 0.0f;
        g_loc_sum = 0.0;
        g_npos    = 0;
        __threadfence();
        g_ticket  = 0u;
    }
}

extern "C" void kernel_launch(void* const* d_in, const int* in_sizes, int n_in,
                              void* d_out, int out_size)
{
    const float4* loc_preds   = (const float4*)d_in[0];
    const float4* loc_targets = (const float4*)d_in[1];
    // d_in[2] = cls_preds — provably unused (ce == 0 exactly for C == 1).
    const int*    cls_targets = (const int*)d_in[3];
    const int n_anchors = in_sizes[3];   // B * A = 3,200,000

    ohem_reduce_kernel<<<GRID_BLOCKS, 256>>>(loc_preds, loc_targets,
                                             cls_targets, n_anchors,
                                             (float*)d_out);
}